// round 9
// baseline (speedup 1.0000x reference)
#include <cuda_runtime.h>
#include <cstdint>

// AdaptiveSample, row-window gather:
//   weights: softmax over 15 sampled taps of valid*posw*guide (per pixel) -> smem
//   gather: per (channel, dy) load each row segment ONCE aligned (float2/thread,
//           2 px/thread), neighbors via warp shuffle, taps served by register select.
//   second output = passthrough copy of features.

namespace {
constexpr int H  = 256;
constexpr int W  = 512;
constexpr int C  = 32;
constexpr int B  = 2;
constexpr int S  = 15;
constexpr int KS = 5;
constexpr int KK = 25;
constexpr int HW = H * W;

constexpr int TW  = 64;            // tile width (px)
constexpr int TH  = 8;             // tile height
constexpr int NT  = 256;           // threads: warp = one row, lane owns 2 px
constexpr int TPX = TW * TH;       // 512 px per tile
}

__global__ __launch_bounds__(NT, 4)
void adaptive_sample_kernel(const float* __restrict__ depth,
                            const float* __restrict__ features,
                            const float* __restrict__ guide,
                            const int*   __restrict__ sidx,
                            float* __restrict__ out,
                            float* __restrict__ outf,
                            int do_copy)
{
    __shared__ alignas(16) float wbuf[S * TPX];   // weights [s][pixel-in-tile]  30.7KB
    __shared__ alignas(16) float sgw[32 * 4 * KK];// guide subtile stage         12.8KB
    __shared__ float       sh_posw[S];
    __shared__ int         sh_k[S];
    __shared__ int         sh_cnt[5];
    __shared__ int         sh_item[5 * 16];       // per-dy tap list: dxc | s<<3
    __shared__ signed char sh_dy[S], sh_dx[S];

    const int tid  = threadIdx.x;
    const int lane = tid & 31;
    const int wr   = tid >> 5;                     // warp = tile row
    const int w0   = blockIdx.x * TW;
    const int h0   = blockIdx.y * TH;
    const int b    = blockIdx.z;

    // ---- tap metadata + per-dy grouping (one thread; S=15 trivial) ----
    if (tid == 0) {
        float pw[S];
        float sum = 0.f;
        int cnt[5] = {0, 0, 0, 0, 0};
        #pragma unroll
        for (int s = 0; s < S; ++s) {
            int k  = sidx[s];
            int px = k % KS;
            int py = k / KS;
            float fx = (float)px - 2.f;
            float fy = (float)py - 2.f;
            float v  = __expf(-0.5f * sqrtf(fx * fx + fy * fy));
            pw[s] = v; sum += v;
            sh_k[s]  = k;
            sh_dy[s] = (signed char)(py - 2);
            sh_dx[s] = (signed char)(px - 2);
            sh_item[py * 16 + cnt[py]] = px | (s << 3);   // dxc = px = dx+2
            cnt[py]++;
        }
        #pragma unroll
        for (int d = 0; d < 5; ++d) sh_cnt[d] = cnt[d];
        float inv = 1.f / sum;
        #pragma unroll
        for (int s = 0; s < S; ++s) sh_posw[s] = pw[s] * inv;
    }

    // ---- weight phase: 4 subtiles of 32x4 px ----
    const float* drow = depth + (size_t)b * HW;
    #pragma unroll 1
    for (int sub = 0; sub < 4; ++sub) {
        const int sw = (sub & 1) * 32;
        const int sr = (sub >> 1) * 4;

        // stage guide subtile: 4 rows x 800 contiguous floats
        for (int i4 = tid; i4 < 800; i4 += NT) {
            int r  = i4 / 200;
            int in = i4 - r * 200;
            const float4* src = reinterpret_cast<const float4*>(
                guide + (((size_t)b * H + (h0 + sr + r)) * W + (w0 + sw)) * KK) + in;
            reinterpret_cast<float4*>(sgw)[r * 200 + in] = *src;
        }
        __syncthreads();

        if (tid < 128) {
            const int tx = tid & 31;
            const int ty = tid >> 5;        // 0..3
            const int h  = h0 + sr + ty;
            const int w  = w0 + sw + tx;
            const float* gpix = sgw + (ty * 32 + tx) * KK;

            float wv[S];
            unsigned ibm  = 0u;
            float    gmax = 0.f;   // logits >= 0
            #pragma unroll
            for (int s = 0; s < S; ++s) {
                int dy = (int)sh_dy[s], dx = (int)sh_dx[s];
                int hh = h + dy, ww = w + dx;
                bool ib = ((unsigned)hh < (unsigned)H) && ((unsigned)ww < (unsigned)W);
                float d = ib ? __ldg(drow + hh * W + ww) : 0.f;
                bool valid = ib && (d > 0.f) && (d < 192.0f);
                float logit = valid ? sh_posw[s] * gpix[sh_k[s]] : 0.f;
                wv[s] = logit;
                gmax  = fmaxf(gmax, logit);
                ibm  |= (unsigned)ib << s;
            }
            float esum = 0.f;
            #pragma unroll
            for (int s = 0; s < S; ++s) { wv[s] = __expf(wv[s] - gmax); esum += wv[s]; }
            float inv = 1.f / esum;

            const int p = (sr + ty) * TW + sw + tx;
            #pragma unroll
            for (int s = 0; s < S; ++s)
                wbuf[s * TPX + p] = ((ibm >> s) & 1u) ? wv[s] * inv : 0.f;
        }
        __syncthreads();
    }

    // ---- gather phase: warp = one row; lane owns px (X, X+1) ----
    const int h  = h0 + wr;
    const int X  = w0 + 2 * lane;
    const int p0 = wr * TW + 2 * lane;

    const float* fb = features + (size_t)b * C * HW;
    float*       ob = out      + (size_t)b * C * HW;

    #pragma unroll 1
    for (int q = 0; q < C / 4; ++q) {
        const float* f0 = fb + (size_t)(q * 4) * HW;
        float2 acc[4];
        #pragma unroll
        for (int ch = 0; ch < 4; ++ch) acc[ch] = make_float2(0.f, 0.f);

        #pragma unroll
        for (int dyi = 0; dyi < 5; ++dyi) {
            const int n = sh_cnt[dyi];
            if (n == 0) continue;

            const int hh = min(max(h + dyi - 2, 0), H - 1);
            const size_t ro = (size_t)hh * W;

            float2 Bv[4], av[4], cv[4];
            #pragma unroll
            for (int ch = 0; ch < 4; ++ch) {
                const float* rp = f0 + (size_t)ch * HW + ro;
                Bv[ch] = __ldg(reinterpret_cast<const float2*>(rp + X));
                float2 hl = make_float2(0.f, 0.f), hr = make_float2(0.f, 0.f);
                if (lane == 0)
                    hl = __ldg(reinterpret_cast<const float2*>(rp + max(w0 - 2, 0)));
                if (lane == 31)
                    hr = __ldg(reinterpret_cast<const float2*>(rp + min(w0 + TW, W - 2)));
                av[ch].x = __shfl_up_sync(0xffffffffu, Bv[ch].x, 1);
                av[ch].y = __shfl_up_sync(0xffffffffu, Bv[ch].y, 1);
                cv[ch].x = __shfl_down_sync(0xffffffffu, Bv[ch].x, 1);
                cv[ch].y = __shfl_down_sync(0xffffffffu, Bv[ch].y, 1);
                if (lane == 0)  av[ch] = hl;   // feat[w0-2], feat[w0-1]
                if (lane == 31) cv[ch] = hr;   // feat[w0+64], feat[w0+65]
            }

            for (int i = 0; i < n; ++i) {
                const int item = sh_item[dyi * 16 + i];
                const int s    = item >> 3;
                const int dxc  = item & 7;
                const float2 wt = *reinterpret_cast<const float2*>(&wbuf[s * TPX + p0]);
                float v0[4], v1[4];
                switch (dxc) {
                  case 0:  // dx=-2: cols {X-2, X-1}
                    #pragma unroll
                    for (int ch = 0; ch < 4; ++ch) { v0[ch] = av[ch].x; v1[ch] = av[ch].y; }
                    break;
                  case 1:  // dx=-1: cols {X-1, X}
                    #pragma unroll
                    for (int ch = 0; ch < 4; ++ch) { v0[ch] = av[ch].y; v1[ch] = Bv[ch].x; }
                    break;
                  case 2:  // dx=0: cols {X, X+1}
                    #pragma unroll
                    for (int ch = 0; ch < 4; ++ch) { v0[ch] = Bv[ch].x; v1[ch] = Bv[ch].y; }
                    break;
                  case 3:  // dx=1: cols {X+1, X+2}
                    #pragma unroll
                    for (int ch = 0; ch < 4; ++ch) { v0[ch] = Bv[ch].y; v1[ch] = cv[ch].x; }
                    break;
                  default: // dx=2: cols {X+2, X+3}
                    #pragma unroll
                    for (int ch = 0; ch < 4; ++ch) { v0[ch] = cv[ch].x; v1[ch] = cv[ch].y; }
                    break;
                }
                #pragma unroll
                for (int ch = 0; ch < 4; ++ch) {
                    acc[ch].x = fmaf(wt.x, v0[ch], acc[ch].x);
                    acc[ch].y = fmaf(wt.y, v1[ch], acc[ch].y);
                }
            }
        }

        #pragma unroll
        for (int ch = 0; ch < 4; ++ch)
            *reinterpret_cast<float2*>(ob + (size_t)(q * 4 + ch) * HW + (size_t)h * W + X)
                = acc[ch];
    }

    // ---- passthrough copy, float4 both sides ----
    if (do_copy) {
        float* oc = outf + (size_t)b * C * HW;
        #pragma unroll
        for (int it = 0; it < (C * TPX / 4) / NT; ++it) {   // 4096/256 = 16
            int i   = tid + it * NT;
            int c   = i >> 7;                // 128 float4 per channel tile
            int rem = i & 127;
            int r   = rem >> 4;              // 16 float4 per row
            int q4  = rem & 15;
            size_t off = (size_t)c * HW + (size_t)(h0 + r) * W + w0 + q4 * 4;
            float4 v = __ldg(reinterpret_cast<const float4*>(fb + off));
            *reinterpret_cast<float4*>(oc + off) = v;
        }
    }
}

extern "C" void kernel_launch(void* const* d_in, const int* in_sizes, int n_in,
                              void* d_out, int out_size)
{
    const float* depth    = (const float*)d_in[0];
    const float* features = (const float*)d_in[1];
    const float* guide    = (const float*)d_in[2];
    const int*   sidx     = (const int*)d_in[3];

    float* out = (float*)d_out;
    const int featN = in_sizes[1];                       // B*C*H*W
    const int do_copy = (out_size >= 2 * featN) ? 1 : 0; // tuple output: (out, features)
    float* outf = out + featN;

    dim3 block(NT);
    dim3 grid(W / TW, H / TH, B);
    adaptive_sample_kernel<<<grid, block>>>(depth, features, guide, sidx,
                                            out, outf, do_copy);
}

// round 10
// speedup vs baseline: 1.7262x; 1.7262x over previous
#include <cuda_runtime.h>
#include <cstdint>

// AdaptiveSample, fused + re-phased:
//   1) cp.async guide tile -> smem (async, no reg dependency)
//   2) passthrough copy (float4 gmem->gmem) WHILE guide loads fly
//   3) barrier; per-pixel softmax weights (regs)
//   4) barrier-free gather: 4 tiles of 8 channels, 8-way MLP (best engine, R6-K2)

namespace {
constexpr int H  = 256;
constexpr int W  = 512;
constexpr int C  = 32;
constexpr int B  = 2;
constexpr int S  = 15;
constexpr int KS = 5;
constexpr int KK = 25;
constexpr int HW = H * W;

constexpr int BW = 32;
constexpr int BH = 8;
constexpr int NT = BW * BH;
constexpr int GBUF = BH * BW * KK;      // guide tile floats (6400)
constexpr int GCHUNKS = GBUF / 4;       // 1600 16B chunks
}

__device__ __forceinline__ void cp_async16(uint32_t dst_smem, const void* src) {
    asm volatile("cp.async.ca.shared.global [%0], [%1], 16;\n" :: "r"(dst_smem), "l"(src));
}
__device__ __forceinline__ void cp_commit() { asm volatile("cp.async.commit_group;\n"); }
__device__ __forceinline__ void cp_wait0()  { asm volatile("cp.async.wait_group 0;\n"); }

__global__ __launch_bounds__(NT, 5)
void adaptive_sample_kernel(const float* __restrict__ depth,
                            const float* __restrict__ features,
                            const float* __restrict__ guide,
                            const int*   __restrict__ sidx,
                            float* __restrict__ out,
                            float* __restrict__ outf,
                            int do_copy)
{
    __shared__ float       shg[GBUF];
    __shared__ float       sh_posw[S];
    __shared__ int         sh_k[S];
    __shared__ signed char sh_dy[S], sh_dx[S];

    const int tx  = threadIdx.x;
    const int ty  = threadIdx.y;
    const int tid = ty * BW + tx;
    const int w0  = blockIdx.x * BW;
    const int h0  = blockIdx.y * BH;
    const int b   = blockIdx.z;

    const uint32_t sg = (uint32_t)__cvta_generic_to_shared(shg);

    // ---- 1) kick off guide tile staging with cp.async (each guide row of this
    //         tile = 800 contiguous floats = 200 x 16B chunks) ----
    {
        const float* grow = guide + ((size_t)b * H + h0) * (size_t)W * KK + (size_t)w0 * KK;
        #pragma unroll
        for (int it = 0; it < (GCHUNKS + NT - 1) / NT; ++it) {   // 7
            int i = tid + it * NT;
            if (i < GCHUNKS) {
                int row = i / 200;
                int in  = i - row * 200;
                cp_async16(sg + (uint32_t)(row * 800 + in * 4) * 4u,
                           grow + (size_t)row * W * KK + in * 4);
            }
        }
        cp_commit();
    }

    // ---- tap metadata (one thread; overlaps cp.async) ----
    if (tid == 0) {
        float pw[S];
        float sum = 0.f;
        #pragma unroll
        for (int s = 0; s < S; ++s) {
            int k  = sidx[s];
            int px = k % KS;
            int py = k / KS;
            float fx = (float)px - 2.f;
            float fy = (float)py - 2.f;
            float v  = __expf(-0.5f * sqrtf(fx * fx + fy * fy));
            pw[s] = v; sum += v;
            sh_k[s]  = k;
            sh_dy[s] = (signed char)(py - 2);
            sh_dx[s] = (signed char)(px - 2);
        }
        float inv = 1.f / sum;
        #pragma unroll
        for (int s = 0; s < S; ++s) sh_posw[s] = pw[s] * inv;
    }

    const float* fbase = features + (size_t)b * C * HW;

    // ---- 2) passthrough copy NOW (hides guide staging latency) ----
    if (do_copy) {
        float* ocbase = outf + (size_t)b * C * HW;
        #pragma unroll
        for (int it = 0; it < (C * BH * BW / 4) / NT; ++it) {   // 8
            int i   = tid + it * NT;
            int c   = i >> 6;
            int rem = i & 63;
            int r   = rem >> 3;
            int q4  = rem & 7;
            size_t off = (size_t)c * HW + (size_t)(h0 + r) * W + w0 + q4 * 4;
            float4 v = __ldg(reinterpret_cast<const float4*>(fbase + off));
            *reinterpret_cast<float4*>(ocbase + off) = v;
        }
    }

    cp_wait0();
    __syncthreads();   // guide tile + tap metadata visible

    const int h = h0 + ty;
    const int w = w0 + tx;

    // ---- 3) per-pixel softmax weights (registers) + gmem tap offsets ----
    const float* drow = depth + (size_t)b * HW;
    const float* gpix = shg + (ty * BW + tx) * KK;   // lane stride 25: conflict-free

    float wv[S];
    int   offs[S];
    unsigned ibm  = 0u;
    float    gmax = 0.f;  // logits >= 0
    #pragma unroll
    for (int s = 0; s < S; ++s) {
        int dy = (int)sh_dy[s], dx = (int)sh_dx[s];
        int hh = h + dy, ww = w + dx;
        bool ib = ((unsigned)hh < (unsigned)H) && ((unsigned)ww < (unsigned)W);
        float d = ib ? __ldg(drow + hh * W + ww) : 0.f;
        bool valid = ib && (d > 0.f) && (d < 192.0f);
        float logit = valid ? sh_posw[s] * gpix[sh_k[s]] : 0.f;
        wv[s] = logit;
        gmax  = fmaxf(gmax, logit);
        ibm  |= (unsigned)ib << s;
        offs[s] = ib ? (dy * W + dx) : 0;   // clamped: weight is 0 there
    }
    float esum = 0.f;
    #pragma unroll
    for (int s = 0; s < S; ++s) { wv[s] = __expf(wv[s] - gmax); esum += wv[s]; }
    float inv = 1.f / esum;
    #pragma unroll
    for (int s = 0; s < S; ++s)
        wv[s] = ((ibm >> s) & 1u) ? wv[s] * inv : 0.f;  // OOB tap == zero-padded feature

    // ---- 4) barrier-free gather: 4 tiles of 8 channels, 8-way MLP ----
    const size_t pix  = (size_t)h * W + w;
    const float* fpix = fbase + pix;
    float*       opix = out + (size_t)b * C * HW + pix;

    #pragma unroll 1
    for (int ct = 0; ct < C / 8; ++ct) {
        const float* fc = fpix + (size_t)(ct * 8) * HW;
        float a0 = 0.f, a1 = 0.f, a2 = 0.f, a3 = 0.f;
        float a4 = 0.f, a5 = 0.f, a6 = 0.f, a7 = 0.f;
        #pragma unroll
        for (int s = 0; s < S; ++s) {
            float wt = wv[s];
            int   o  = offs[s];
            a0 = fmaf(wt, __ldg(fc + 0 * HW + o), a0);
            a1 = fmaf(wt, __ldg(fc + 1 * HW + o), a1);
            a2 = fmaf(wt, __ldg(fc + 2 * HW + o), a2);
            a3 = fmaf(wt, __ldg(fc + 3 * HW + o), a3);
            a4 = fmaf(wt, __ldg(fc + 4 * HW + o), a4);
            a5 = fmaf(wt, __ldg(fc + 5 * HW + o), a5);
            a6 = fmaf(wt, __ldg(fc + 6 * HW + o), a6);
            a7 = fmaf(wt, __ldg(fc + 7 * HW + o), a7);
        }
        float* oc = opix + (size_t)(ct * 8) * HW;
        oc[0 * HW] = a0; oc[1 * HW] = a1; oc[2 * HW] = a2; oc[3 * HW] = a3;
        oc[4 * HW] = a4; oc[5 * HW] = a5; oc[6 * HW] = a6; oc[7 * HW] = a7;
    }
}

extern "C" void kernel_launch(void* const* d_in, const int* in_sizes, int n_in,
                              void* d_out, int out_size)
{
    const float* depth    = (const float*)d_in[0];
    const float* features = (const float*)d_in[1];
    const float* guide    = (const float*)d_in[2];
    const int*   sidx     = (const int*)d_in[3];

    float* out = (float*)d_out;
    const int featN = in_sizes[1];                       // B*C*H*W
    const int do_copy = (out_size >= 2 * featN) ? 1 : 0; // tuple output: (out, features)
    float* outf = out + featN;

    dim3 block(BW, BH);
    dim3 grid(W / BW, H / BH, B);
    adaptive_sample_kernel<<<grid, block>>>(depth, features, guide, sidx,
                                            out, outf, do_copy);
}